// round 7
// baseline (speedup 1.0000x reference)
#include <cuda_runtime.h>
#include <math.h>

#define MM      128
#define MP1     129
#define DD      24
#define NN      512
#define LL      256
#define MSTRIDE 132

#define NULLF   (-1.0e30f)
#define LOG2E   1.4426950408889634f
#define LN2     0.6931471805599453f

// ---------------- device-global scratch (all log2 domain) ----------------
__device__ __align__(16) float g_cb0[MSTRIDE];
__device__ __align__(16) float g_cb1[MSTRIDE];
__device__ __align__(16) float g_w  [MSTRIDE];
__device__ __align__(16) float g_q00[MSTRIDE];
__device__ __align__(16) float g_q10[MSTRIDE];
__device__ __align__(16) float g_q01[MSTRIDE];
__device__ __align__(16) float g_q11[MSTRIDE];
__device__ __align__(16) float g_c0 [MSTRIDE];
__device__ __align__(16) float g_c1 [MSTRIDE];
__device__ __align__(16) float g_Ea [(DD + 1) * MSTRIDE];  // +1 zero row for padding
__device__ __align__(16) float g_Ei [(DD + 1) * MSTRIDE];
__device__ __align__(16) int   g_tok[NN * LL];

// ---- fast log2-domain primitives ----
__device__ __forceinline__ float ex2f(float x) {
    float r; asm("ex2.approx.ftz.f32 %0, %1;" : "=f"(r) : "f"(x)); return r;
}
__device__ __forceinline__ float lg2f(float x) {
    float r; asm("lg2.approx.ftz.f32 %0, %1;" : "=f"(r) : "f"(x)); return r;
}
__device__ __forceinline__ float lse2(float a, float b) {
    float m = fmaxf(a, b);
    float d = -fabsf(a - b);
    return m + lg2f(1.0f + ex2f(d));
}
__device__ __forceinline__ float lse3(float a, float b, float c) {
    float m = fmaxf(fmaxf(a, b), c);
    float s = ex2f(a - m) + ex2f(b - m) + ex2f(c - m);
    return m + lg2f(s);
}
__device__ __forceinline__ float lse4(float a, float b, float c, float d) {
    float m = fmaxf(fmaxf(a, b), fmaxf(c, d));
    float s = (ex2f(a - m) + ex2f(b - m)) + (ex2f(c - m) + ex2f(d - m));
    return m + lg2f(s);
}
__device__ __forceinline__ float lse5(float a, float b, float c, float d, float e) {
    float m = fmaxf(fmaxf(fmaxf(a, b), fmaxf(c, d)), e);
    float s = (ex2f(a - m) + ex2f(b - m)) + (ex2f(c - m) + ex2f(d - m)) + ex2f(e - m);
    return m + lg2f(s);
}
__device__ __forceinline__ float lse2_acc(float a, float b) {  // accurate, prep only
    float mx = fmaxf(a, b);
    float mn = fminf(a, b);
    return mx + log1pf(expf(mn - mx));
}

// ---------------- fused prep: blocks 0..NN-1 = tokens, block NN = constants ----------------
__global__ void prep(const float* __restrict__ anc,
                     const float* __restrict__ ins,
                     const float* __restrict__ rr,
                     const float* __restrict__ uu,
                     const float* __restrict__ data) {
    int b = blockIdx.x;
    if (b < NN) {
        int t = threadIdx.x;                       // 0..255
        const float* row = data + ((size_t)(b * LL + t)) * DD;
        int tk = DD;                                // padding -> zero emission row
        for (int d = 0; d < DD; d++)
            if (row[d] > 0.5f) tk = d;
        g_tok[b * LL + t] = tk;
        return;
    }

    int m = threadIdx.x;
    if (m < MSTRIDE) {                              // zero padding row (tk == DD)
        g_Ea[DD * MSTRIDE + m] = 0.f;
        g_Ei[DD * MSTRIDE + m] = 0.f;
    }
    if (m >= MP1) return;

    {
        const float* ar = anc + m * DD;
        float mx = -1e30f;
        for (int d = 0; d < DD; d++) mx = fmaxf(mx, ar[d]);
        float s = 0.f;
        for (int d = 0; d < DD; d++) s += expf(ar[d] - mx);
        float lse = mx + logf(s);
        for (int d = 0; d < DD; d++) g_Ea[d * MSTRIDE + m] = (ar[d] - lse) * LOG2E;
    }
    {
        const float* ir = ins + m * DD;
        float mx = -1e30f;
        for (int d = 0; d < DD; d++) mx = fmaxf(mx, ir[d]);
        float s = 0.f;
        for (int d = 0; d < DD; d++) s += expf(ir[d] - mx);
        float lse = mx + logf(s);
        for (int d = 0; d < DD; d++) g_Ei[d * MSTRIDE + m] = (ir[d] - lse) * LOG2E;
    }

    float r[3][2], u[3][2];
    for (int c = 0; c < 3; c++) {
        float x0 = rr[(m * 3 + c) * 2 + 0];
        float x1 = rr[(m * 3 + c) * 2 + 1];
        float l2 = lse2_acc(x0, x1);
        r[c][0] = x0 - l2; r[c][1] = x1 - l2;
        x0 = uu[(m * 3 + c) * 2 + 0];
        x1 = uu[(m * 3 + c) * 2 + 1];
        l2 = lse2_acc(x0, x1);
        u[c][0] = x0 - l2; u[c][1] = x1 - l2;
    }
    g_w  [m] = (r[2][0] + u[2][1]) * LOG2E;
    g_cb0[m] = (r[0][0] + u[0][1]) * LOG2E;
    g_cb1[m] = (r[1][0] + u[1][1]) * LOG2E;
    g_q00[m] = (r[0][0] + u[0][0]) * LOG2E;
    g_q10[m] = (r[1][0] + u[1][0]) * LOG2E;
    g_q01[m] = (r[0][1]) * LOG2E;
    g_q11[m] = (r[1][1]) * LOG2E;
    g_c0 [m] = (r[2][0] + u[2][0]) * LOG2E;
    g_c1 [m] = (r[2][1]) * LOG2E;
}

// ------- main: 4 warps/block (one per SMSP), TWO sequences per warp (ILP) -------
__global__ void __launch_bounds__(128) hmm_fwd(float* __restrict__ out) {
    const unsigned FULL = 0xffffffffu;
    const int wid = threadIdx.x >> 5;               // warp -> SMSP wid%4
    const int nA = (blockIdx.x * 4 + wid) * 2;      // first sequence of this warp
    const int nB = nA + 1;
    const int l = threadIdx.x & 31;
    const int m0 = l * 4;
    const bool lastlane = (l == 31);

    // shared per-element constants (one copy for both sequences)
    float cb0[4], cb1[4], wv[4], q00[4], q10[4], q01[4], q11[4], c0[4], c1[4];
#pragma unroll
    for (int q = 0; q < 4; q++) {
        int m = m0 + q;
        cb0[q] = g_cb0[m]; cb1[q] = g_cb1[m]; wv[q] = g_w[m];
        q00[q] = g_q00[m]; q10[q] = g_q10[m];
        q01[q] = g_q01[m]; q11[q] = g_q11[m];
        c0[q]  = g_c0[m];  c1[q]  = g_c1[m];
    }
    const float q00x = lastlane ? g_q00[MM] : NULLF;
    const float q10x = lastlane ? g_q10[MM] : NULLF;
    const float q01x = lastlane ? g_q01[MM] : NULLF;
    const float q11x = lastlane ? g_q11[MM] : NULLF;
    const float c0x  = lastlane ? g_c0 [MM] : NULLF;
    const float c1x  = lastlane ? g_c1 [MM] : NULLF;

    const float wv0 = wv[0], wv1 = wv[1], wv2 = wv[2], wv3 = wv[3];
    const float W23  = wv2 + wv3;
    const float W12  = wv1 + wv2;
    const float Wp1  = wv0 + wv1;
    const float Wp2  = Wp1 + wv2;
    const float W123 = wv1 + W23;
    const float cbW0 = cb0[0] + W123;
    const float cbW1 = cb1[0] + W123;
    const float Lw   = wv0 + W123;

    // inclusive prefix P (once; radix-2 shfl scan)
    float P = Lw;
#pragma unroll
    for (int d = 1; d < 32; d <<= 1) {
        float o = __shfl_up_sync(FULL, P, d);
        if (l >= d) P += o;
    }
    float Pm1  = __shfl_up_sync(FULL, P, 1);
    float Pm2  = __shfl_up_sync(FULL, P, 2);
    float Pm3  = __shfl_up_sync(FULL, P, 3);
    float Pm4  = __shfl_up_sync(FULL, P, 4);
    float Pm8  = __shfl_up_sync(FULL, P, 8);
    float Pm12 = __shfl_up_sync(FULL, P, 12);
    float Pm16 = __shfl_up_sync(FULL, P, 16);
    const float K01 = (l >= 1 ) ? P - Pm1  : NULLF;
    const float K02 = (l >= 2 ) ? P - Pm2  : NULLF;
    const float K03 = (l >= 3 ) ? P - Pm3  : NULLF;
    const float K11 = (l >= 4 ) ? P - Pm4  : NULLF;
    const float K12 = (l >= 8 ) ? P - Pm8  : NULLF;
    const float K13 = (l >= 12) ? P - Pm12 : NULLF;
    const float K21 = (l >= 16) ? P - Pm16 : NULLF;

    // per-sequence state
    float Aa0[4] = {NULLF, NULLF, NULLF, NULLF};
    float Aa1[4] = {NULLF, NULLF, NULLF, NULLF};
    float Aa0x = NULLF, Aa1x = NULLF, Asrc = 0.0f;
    float Ba0[4] = {NULLF, NULLF, NULLF, NULLF};
    float Ba1[4] = {NULLF, NULLF, NULLF, NULLF};
    float Ba0x = NULLF, Ba1x = NULLF, Bsrc = 0.0f;

    const int* tnA = g_tok + nA * LL;
    const int* tnB = g_tok + nB * LL;

    // one HMM step for one sequence
    auto step = [&](float (&a0)[4], float (&a1)[4], float& a0x, float& a1x,
                    float& lane0src, int tko) {
        float atop = __shfl_up_sync(FULL, a0[3], 1);
        if (l == 0) atop = lane0src;

        float b0 = lse2(atop  + cb0[0], a1[0] + cb1[0]);
        float b1 = lse2(a0[0] + cb0[1], a1[1] + cb1[1]);
        float b2 = lse2(a0[1] + cb0[2], a1[2] + cb1[2]);
        float b3 = lse2(a0[2] + cb0[3], a1[3] + cb1[3]);

        float Bs = lse5(atop + cbW0, a1[0] + cbW1, b1 + W23, b2 + wv3, b3);

        float o1 = __shfl_up_sync(FULL, Bs, 1);
        float o2 = __shfl_up_sync(FULL, Bs, 2);
        float o3 = __shfl_up_sync(FULL, Bs, 3);
        Bs = lse4(Bs, o1 + K01, o2 + K02, o3 + K03);
        o1 = __shfl_up_sync(FULL, Bs, 4);
        o2 = __shfl_up_sync(FULL, Bs, 8);
        o3 = __shfl_up_sync(FULL, Bs, 12);
        Bs = lse4(Bs, o1 + K11, o2 + K12, o3 + K13);
        o1 = __shfl_up_sync(FULL, Bs, 16);
        Bs = lse2(Bs, o1 + K21);

        float Bex = __shfl_up_sync(FULL, Bs, 1);
        if (l == 0) Bex = NULLF;

        float B1 = lse2(Bex + wv0, b0);
        float B2 = lse3(Bex + Wp1, b0 + wv1, b1);
        float B3 = lse4(Bex + Wp2, b0 + W12, b1 + wv2, b2);

        const float4 ea = *(const float4*)(g_Ea + tko + m0);
        const float4 ei = *(const float4*)(g_Ei + tko + m0);
        const float eax = g_Ea[tko + MM];
        const float eix = g_Ei[tko + MM];

        float na00 = lse3(atop  + q00[0], a1[0] + q10[0], Bex + c0[0]) + ea.x;
        float na10 = lse3(atop  + q01[0], a1[0] + q11[0], Bex + c1[0]) + ei.x;
        float na01 = lse3(a0[0] + q00[1], a1[1] + q10[1], B1  + c0[1]) + ea.y;
        float na11 = lse3(a0[0] + q01[1], a1[1] + q11[1], B1  + c1[1]) + ei.y;
        float na02 = lse3(a0[1] + q00[2], a1[2] + q10[2], B2  + c0[2]) + ea.z;
        float na12 = lse3(a0[1] + q01[2], a1[2] + q11[2], B2  + c1[2]) + ei.z;
        float na03 = lse3(a0[2] + q00[3], a1[3] + q10[3], B3  + c0[3]) + ea.w;
        float na13 = lse3(a0[2] + q01[3], a1[3] + q11[3], B3  + c1[3]) + ei.w;
        float na0x = lse3(a0[3] + q00x, a1x + q10x, Bs + c0x) + eax;
        float na1x = lse3(a0[3] + q01x, a1x + q11x, Bs + c1x) + eix;

        a0[0] = na00; a0[1] = na01; a0[2] = na02; a0[3] = na03;
        a1[0] = na10; a1[1] = na11; a1[2] = na12; a1[3] = na13;
        a0x = na0x; a1x = na1x;
        lane0src = NULLF;
    };

    for (int tt = 0; tt < LL; tt += 4) {
        const int4 tkA = *(const int4*)(tnA + tt);
        const int4 tkB = *(const int4*)(tnB + tt);
        const int tksA[4] = {tkA.x, tkA.y, tkA.z, tkA.w};
        const int tksB[4] = {tkB.x, tkB.y, tkB.z, tkB.w};

#pragma unroll
        for (int k = 0; k < 4; k++) {
            step(Aa0, Aa1, Aa0x, Aa1x, Asrc, tksA[k] * MSTRIDE);
            step(Ba0, Ba1, Ba0x, Ba1x, Bsrc, tksB[k] * MSTRIDE);
        }
    }

    // final logsumexp for both sequences
    auto finish = [&](float (&a0)[4], float (&a1)[4], float a0x, float a1x) -> float {
        float mx = fmaxf(a0x, a1x);
#pragma unroll
        for (int q = 0; q < 4; q++) mx = fmaxf(mx, fmaxf(a0[q], a1[q]));
#pragma unroll
        for (int d = 16; d; d >>= 1) mx = fmaxf(mx, __shfl_xor_sync(FULL, mx, d));
        float s = exp2f(a0x - mx) + exp2f(a1x - mx);
#pragma unroll
        for (int q = 0; q < 4; q++) s += exp2f(a0[q] - mx) + exp2f(a1[q] - mx);
#pragma unroll
        for (int d = 16; d; d >>= 1) s += __shfl_xor_sync(FULL, s, d);
        return (mx + log2f(s)) * LN2;
    };

    float rA = finish(Aa0, Aa1, Aa0x, Aa1x);
    float rB = finish(Ba0, Ba1, Ba0x, Ba1x);
    if (l == 0) {
        out[nA] = rA;
        out[nB] = rB;
    }
}

// ---------------- entry point ----------------
extern "C" void kernel_launch(void* const* d_in, const int* in_sizes, int n_in,
                              void* d_out, int out_size) {
    const float* anc  = (const float*)d_in[0];  // (129, 24)
    const float* ins  = (const float*)d_in[1];  // (129, 24)
    const float* rr   = (const float*)d_in[2];  // (129, 3, 2)
    const float* uu   = (const float*)d_in[3];  // (129, 3, 2)
    const float* data = (const float*)d_in[4];  // (512, 256, 24)
    (void)in_sizes; (void)n_in; (void)out_size;

    prep<<<NN + 1, LL>>>(anc, ins, rr, uu, data);
    hmm_fwd<<<NN / 8, 128>>>((float*)d_out);   // 64 blocks x 4 warps x 2 seqs
}

// round 8
// speedup vs baseline: 2.4530x; 2.4530x over previous
#include <cuda_runtime.h>
#include <math.h>

#define MM      128
#define MP1     129
#define DD      24
#define NN      512
#define LL      256
#define MSTRIDE 132

#define EMINE   (-(1 << 27))
#define LOG2E   1.4426950408889634f
#define LN2     0.6931471805599453f

// ---------------- device-global scratch (probability domain) ----------------
__device__ __align__(16) float g_cb0[MSTRIDE];
__device__ __align__(16) float g_cb1[MSTRIDE];
__device__ __align__(16) float g_w  [MSTRIDE];
__device__ __align__(16) float g_q00[MSTRIDE];
__device__ __align__(16) float g_q10[MSTRIDE];
__device__ __align__(16) float g_q01[MSTRIDE];
__device__ __align__(16) float g_q11[MSTRIDE];
__device__ __align__(16) float g_c0 [MSTRIDE];
__device__ __align__(16) float g_c1 [MSTRIDE];
__device__ __align__(16) float g_Ea [(DD + 1) * MSTRIDE];  // emission probs; row DD = 1.0 (padding)
__device__ __align__(16) float g_Ei [(DD + 1) * MSTRIDE];
__device__ __align__(16) int   g_tok[NN * LL];

// ---- extended float primitives: value = m * 2^e, m >= 0 ----
// scale m by 2^k (k <= 0 always); flush to 0 on underflow past denormals.
__device__ __forceinline__ float escale(float x, int k) {
    k = (k < -140) ? -140 : k;
    int b = __float_as_int(x) + (k << 23);
    return (b <= 0x00800000) ? 0.0f : __int_as_float(b);
}
// renormalize mantissa to [1,2); zero -> canonical NULL
__device__ __forceinline__ void enorm(float& m, int& e) {
    int b = __float_as_int(m);
    if (b <= 0x00800000) { m = 0.0f; e = EMINE; }
    else {
        int k = (b >> 23) - 127;
        e += k;
        m = __int_as_float(b - (k << 23));
    }
}

__device__ __forceinline__ float lse2_acc(float a, float b) {  // prep only
    float mx = fmaxf(a, b);
    float mn = fminf(a, b);
    return mx + log1pf(expf(mn - mx));
}

// ---------------- fused prep: blocks 0..NN-1 = tokens, block NN = constants ----------------
__global__ void prep(const float* __restrict__ anc,
                     const float* __restrict__ ins,
                     const float* __restrict__ rr,
                     const float* __restrict__ uu,
                     const float* __restrict__ data) {
    int b = blockIdx.x;
    if (b < NN) {
        int t = threadIdx.x;
        const float* row = data + ((size_t)(b * LL + t)) * DD;
        int tk = DD;                                // padding -> emission 1.0 row
        for (int d = 0; d < DD; d++)
            if (row[d] > 0.5f) tk = d;
        g_tok[b * LL + t] = tk;
        return;
    }

    int m = threadIdx.x;
    if (m < MSTRIDE) {                              // padding row: prob 1
        g_Ea[DD * MSTRIDE + m] = 1.0f;
        g_Ei[DD * MSTRIDE + m] = 1.0f;
    }
    if (m >= MP1) return;

    {
        const float* ar = anc + m * DD;
        float mx = -1e30f;
        for (int d = 0; d < DD; d++) mx = fmaxf(mx, ar[d]);
        float s = 0.f;
        for (int d = 0; d < DD; d++) s += expf(ar[d] - mx);
        float lse = mx + logf(s);
        for (int d = 0; d < DD; d++) g_Ea[d * MSTRIDE + m] = expf(ar[d] - lse);
    }
    {
        const float* ir = ins + m * DD;
        float mx = -1e30f;
        for (int d = 0; d < DD; d++) mx = fmaxf(mx, ir[d]);
        float s = 0.f;
        for (int d = 0; d < DD; d++) s += expf(ir[d] - mx);
        float lse = mx + logf(s);
        for (int d = 0; d < DD; d++) g_Ei[d * MSTRIDE + m] = expf(ir[d] - lse);
    }

    float r[3][2], u[3][2];
    for (int c = 0; c < 3; c++) {
        float x0 = rr[(m * 3 + c) * 2 + 0];
        float x1 = rr[(m * 3 + c) * 2 + 1];
        float l2 = lse2_acc(x0, x1);
        r[c][0] = x0 - l2; r[c][1] = x1 - l2;
        x0 = uu[(m * 3 + c) * 2 + 0];
        x1 = uu[(m * 3 + c) * 2 + 1];
        l2 = lse2_acc(x0, x1);
        u[c][0] = x0 - l2; u[c][1] = x1 - l2;
    }
    g_w  [m] = expf(r[2][0] + u[2][1]);
    g_cb0[m] = expf(r[0][0] + u[0][1]);
    g_cb1[m] = expf(r[1][0] + u[1][1]);
    g_q00[m] = expf(r[0][0] + u[0][0]);
    g_q10[m] = expf(r[1][0] + u[1][0]);
    g_q01[m] = expf(r[0][1]);
    g_q11[m] = expf(r[1][1]);
    g_c0 [m] = expf(r[2][0] + u[2][0]);
    g_c1 [m] = expf(r[2][1]);
}

// ---------------- main: 4 warps/block (one per SMSP), one sequence per warp ----------------
__global__ void __launch_bounds__(128) hmm_fwd(float* __restrict__ out) {
    const unsigned FULL = 0xffffffffu;
    const int wid = threadIdx.x >> 5;
    const int n = blockIdx.x * 4 + wid;
    const int l = threadIdx.x & 31;
    const int m0 = l * 4;
    const bool lastlane = (l == 31);

    // per-element probability constants
    float cb0[4], cb1[4], wv[4], q00[4], q10[4], q01[4], q11[4], c0[4], c1[4];
#pragma unroll
    for (int q = 0; q < 4; q++) {
        int m = m0 + q;
        cb0[q] = g_cb0[m]; cb1[q] = g_cb1[m]; wv[q] = g_w[m];
        q00[q] = g_q00[m]; q10[q] = g_q10[m];
        q01[q] = g_q01[m]; q11[q] = g_q11[m];
        c0[q]  = g_c0[m];  c1[q]  = g_c1[m];
    }
    // m=128 constants: zero prob off lane 31 (inert)
    const float q00x = lastlane ? g_q00[MM] : 0.f;
    const float q10x = lastlane ? g_q10[MM] : 0.f;
    const float q01x = lastlane ? g_q01[MM] : 0.f;
    const float q11x = lastlane ? g_q11[MM] : 0.f;
    const float c0x  = lastlane ? g_c0 [MM] : 0.f;
    const float c1x  = lastlane ? g_c1 [MM] : 0.f;

    const float wv0 = wv[0], wv1 = wv[1], wv2 = wv[2], wv3 = wv[3];
    const float W23  = wv2 * wv3;
    const float W12  = wv1 * wv2;
    const float Wp1  = wv0 * wv1;
    const float Wp2  = Wp1 * wv2;
    const float W123 = wv1 * W23;
    const float cbW0 = cb0[0] * W123;
    const float cbW1 = cb1[0] * W123;

    // lane-aggregate multiplier in log2; warp prefix; K constants as (m, e) pairs
    float Lwl = log2f(wv0 * W123);
    float P = Lwl;
#pragma unroll
    for (int d = 1; d < 32; d <<= 1) {
        float o = __shfl_up_sync(FULL, P, d);
        if (l >= d) P += o;
    }
    float Km[7]; int Ke[7];
    {
        const int offs[7] = {1, 2, 3, 4, 8, 12, 16};
#pragma unroll
        for (int j = 0; j < 7; j++) {
            float Po = __shfl_up_sync(FULL, P, offs[j]);
            if (l >= offs[j]) {
                float Kl = P - Po;
                float fe = floorf(Kl);
                Ke[j] = (int)fe;
                Km[j] = exp2f(Kl - fe);
            } else { Km[j] = 0.f; Ke[j] = EMINE; }
        }
    }

    // state: (mantissa, exponent) per state
    float a0m[4] = {0.f, 0.f, 0.f, 0.f}, a1m[4] = {0.f, 0.f, 0.f, 0.f};
    int   a0e[4] = {EMINE, EMINE, EMINE, EMINE}, a1e[4] = {EMINE, EMINE, EMINE, EMINE};
    float axm0 = 0.f, axm1 = 0.f;
    int   axe0 = EMINE, axe1 = EMINE;
    float srcm = 1.0f; int srce = 0;     // virtual source at t=0

    const int* tn = g_tok + n * LL;

    for (int tt = 0; tt < LL; tt += 4) {
        const int4 tk4 = *(const int4*)(tn + tt);
        const int tks[4] = {tk4.x, tk4.y, tk4.z, tk4.w};

#pragma unroll
        for (int k = 0; k < 4; k++) {
            const int tko = tks[k] * MSTRIDE;

            float atopm = __shfl_up_sync(FULL, a0m[3], 1);
            int   atope = __shfl_up_sync(FULL, a0e[3], 1);
            if (l == 0) { atopm = srcm; atope = srce; }

            // per-element: align (P, I) once; derive b, t0, t1
            float bm[4], t0[4], t1[4], u0;
            int e2[4];
#pragma unroll
            for (int i = 0; i < 4; i++) {
                float Pm = (i == 0) ? atopm : a0m[i - 1];
                int   Pe = (i == 0) ? atope : a0e[i - 1];
                int e = max(Pe, a1e[i]);
                float ps = escale(Pm, Pe - e);
                float is = escale(a1m[i], a1e[i] - e);
                e2[i] = e;
                bm[i] = ps * cb0[i] + is * cb1[i];
                t0[i] = ps * q00[i] + is * q10[i];
                t1[i] = ps * q01[i] + is * q11[i];
                if (i == 0) u0 = ps * cbW0 + is * cbW1;
            }
            // m=128 element alignment
            int e2x = max(a0e[3], axe1);
            float psx = escale(a0m[3], a0e[3] - e2x);
            float isx = escale(axm1, axe1 - e2x);
            float t0x = psx * q00x + isx * q10x;
            float t1x = psx * q01x + isx * q11x;

            // lane aggregate injection Bs
            int Bse = max(max(e2[0], e2[1]), max(e2[2], e2[3]));
            float Bsm = escale(u0, e2[0] - Bse) + escale(bm[1] * W23, e2[1] - Bse)
                      + escale(bm[2] * wv3, e2[2] - Bse) + escale(bm[3], e2[3] - Bse);

            // radix-4 warp scan over (m, e) affine values
            {
                float o1m = __shfl_up_sync(FULL, Bsm, 1);
                int   o1e = __shfl_up_sync(FULL, Bse, 1);
                float o2m = __shfl_up_sync(FULL, Bsm, 2);
                int   o2e = __shfl_up_sync(FULL, Bse, 2);
                float o3m = __shfl_up_sync(FULL, Bsm, 3);
                int   o3e = __shfl_up_sync(FULL, Bse, 3);
                float p1 = o1m * Km[0]; int q1 = o1e + Ke[0];
                float p2 = o2m * Km[1]; int q2 = o2e + Ke[1];
                float p3 = o3m * Km[2]; int q3 = o3e + Ke[2];
                int E = max(max(Bse, q1), max(q2, q3));
                Bsm = escale(Bsm, Bse - E) + escale(p1, q1 - E)
                    + escale(p2, q2 - E) + escale(p3, q3 - E);
                Bse = E;

                o1m = __shfl_up_sync(FULL, Bsm, 4);
                o1e = __shfl_up_sync(FULL, Bse, 4);
                o2m = __shfl_up_sync(FULL, Bsm, 8);
                o2e = __shfl_up_sync(FULL, Bse, 8);
                o3m = __shfl_up_sync(FULL, Bsm, 12);
                o3e = __shfl_up_sync(FULL, Bse, 12);
                p1 = o1m * Km[3]; q1 = o1e + Ke[3];
                p2 = o2m * Km[4]; q2 = o2e + Ke[4];
                p3 = o3m * Km[5]; q3 = o3e + Ke[5];
                E = max(max(Bse, q1), max(q2, q3));
                Bsm = escale(Bsm, Bse - E) + escale(p1, q1 - E)
                    + escale(p2, q2 - E) + escale(p3, q3 - E);
                Bse = E;

                o1m = __shfl_up_sync(FULL, Bsm, 16);
                o1e = __shfl_up_sync(FULL, Bse, 16);
                p1 = o1m * Km[6]; q1 = o1e + Ke[6];
                E = max(Bse, q1);
                Bsm = escale(Bsm, Bse - E) + escale(p1, q1 - E);
                Bse = E;
            }
            float Bexm = __shfl_up_sync(FULL, Bsm, 1);
            int   Bexe = __shfl_up_sync(FULL, Bse, 1);
            if (l == 0) { Bexm = 0.f; Bexe = EMINE; }

            // per-element chain values B1..B3 (B0 = Bex)
            int Be1 = max(Bexe, e2[0]);
            float B1m = escale(Bexm * wv0, Bexe - Be1) + escale(bm[0], e2[0] - Be1);
            int Be2 = max(max(Bexe, e2[0]), e2[1]);
            float B2m = escale(Bexm * Wp1, Bexe - Be2) + escale(bm[0] * wv1, e2[0] - Be2)
                      + escale(bm[1], e2[1] - Be2);
            int Be3 = max(max(Bexe, e2[0]), max(e2[1], e2[2]));
            float B3m = escale(Bexm * Wp2, Bexe - Be3) + escale(bm[0] * W12, e2[0] - Be3)
                      + escale(bm[1] * wv2, e2[1] - Be3) + escale(bm[2], e2[2] - Be3);

            // emission probs
            const float4 ea = *(const float4*)(g_Ea + tko + m0);
            const float4 ei = *(const float4*)(g_Ei + tko + m0);
            const float eax = g_Ea[tko + MM];
            const float eix = g_Ei[tko + MM];
            const float eav[4] = {ea.x, ea.y, ea.z, ea.w};
            const float eiv[4] = {ei.x, ei.y, ei.z, ei.w};
            const float Bmv[4] = {Bexm, B1m, B2m, B3m};
            const int   Bev[4] = {Bexe, Be1, Be2, Be3};

            // new alphas
            float n0m[4], n1m[4]; int n0e[4], n1e[4];
#pragma unroll
            for (int i = 0; i < 4; i++) {
                int E = max(e2[i], Bev[i]);
                float zs = escale(Bmv[i], Bev[i] - E);
                int kk = e2[i] - E;
                float s0 = escale(t0[i], kk) + zs * c0[i];
                float s1 = escale(t1[i], kk) + zs * c1[i];
                n0m[i] = s0 * eav[i]; n0e[i] = E;
                n1m[i] = s1 * eiv[i]; n1e[i] = E;
                enorm(n0m[i], n0e[i]);
                enorm(n1m[i], n1e[i]);
            }
            // m=128 pair (B = inclusive Bs)
            {
                int E = max(e2x, Bse);
                float zs = escale(Bsm, Bse - E);
                int kk = e2x - E;
                float s0 = escale(t0x, kk) + zs * c0x;
                float s1 = escale(t1x, kk) + zs * c1x;
                axm0 = s0 * eax; axe0 = E;
                axm1 = s1 * eix; axe1 = E;
                enorm(axm0, axe0);
                enorm(axm1, axe1);
            }
#pragma unroll
            for (int i = 0; i < 4; i++) {
                a0m[i] = n0m[i]; a0e[i] = n0e[i];
                a1m[i] = n1m[i]; a1e[i] = n1e[i];
            }
            srcm = 0.f; srce = EMINE;
        }
    }

    // final logsumexp over all states (mantissas are in [1,2) or NULL)
    int emax = max(axe0, axe1);
#pragma unroll
    for (int q = 0; q < 4; q++) emax = max(emax, max(a0e[q], a1e[q]));
#pragma unroll
    for (int d = 16; d; d >>= 1) emax = max(emax, __shfl_xor_sync(FULL, emax, d));

    float s = escale(axm0, axe0 - emax) + escale(axm1, axe1 - emax);
#pragma unroll
    for (int q = 0; q < 4; q++)
        s += escale(a0m[q], a0e[q] - emax) + escale(a1m[q], a1e[q] - emax);
#pragma unroll
    for (int d = 16; d; d >>= 1) s += __shfl_xor_sync(FULL, s, d);

    if (l == 0) out[n] = ((float)emax + log2f(s)) * LN2;
}

// ---------------- entry point ----------------
extern "C" void kernel_launch(void* const* d_in, const int* in_sizes, int n_in,
                              void* d_out, int out_size) {
    const float* anc  = (const float*)d_in[0];  // (129, 24)
    const float* ins  = (const float*)d_in[1];  // (129, 24)
    const float* rr   = (const float*)d_in[2];  // (129, 3, 2)
    const float* uu   = (const float*)d_in[3];  // (129, 3, 2)
    const float* data = (const float*)d_in[4];  // (512, 256, 24)
    (void)in_sizes; (void)n_in; (void)out_size;

    prep<<<NN + 1, LL>>>(anc, ins, rr, uu, data);
    hmm_fwd<<<NN / 4, 128>>>((float*)d_out);
}

// round 9
// speedup vs baseline: 2.7640x; 1.1268x over previous
#include <cuda_runtime.h>
#include <math.h>

#define MM      128
#define MP1     129
#define DD      24
#define NN      512
#define LL      256
#define MSTRIDE 132

#define EMINE   (-(1 << 27))
#define LOG2E   1.4426950408889634f
#define LN2     0.6931471805599453f

// ---------------- device-global scratch (probability domain) ----------------
__device__ __align__(16) float g_cb0[MSTRIDE];
__device__ __align__(16) float g_cb1[MSTRIDE];
__device__ __align__(16) float g_w  [MSTRIDE];
__device__ __align__(16) float g_q00[MSTRIDE];
__device__ __align__(16) float g_q10[MSTRIDE];
__device__ __align__(16) float g_q01[MSTRIDE];
__device__ __align__(16) float g_q11[MSTRIDE];
__device__ __align__(16) float g_c0 [MSTRIDE];
__device__ __align__(16) float g_c1 [MSTRIDE];
__device__ __align__(16) float g_Ea [(DD + 1) * MSTRIDE];  // emission probs; row DD = 1.0 (padding)
__device__ __align__(16) float g_Ei [(DD + 1) * MSTRIDE];
__device__ __align__(16) int   g_tok[NN * LL];

// ---- extended float primitives: value = m * 2^e ----
// scale by 2^k (k <= 0): floor at denormal boundary instead of flush-to-zero.
// "zero" terms become 2^-126-relative junk: negligible vs fp32 logsumexp precision.
__device__ __forceinline__ float escf(float x, int k) {
    k = max(k, -140);
    int b = __float_as_int(x) + (k << 23);
    return __int_as_float(max(b, 0x00800000));
}
// pair renorm: shared exponent, normalize by the larger mantissa. No branches.
__device__ __forceinline__ void enorm2(float& m0, float& m1, int& e) {
    float mx = fmaxf(m0, m1);
    int k = (__float_as_int(mx) >> 23) - 127;
    int s = k << 23;
    m0 = __int_as_float(max(__float_as_int(m0) - s, 0));
    m1 = __int_as_float(max(__float_as_int(m1) - s, 0));
    e += k;
}

__device__ __forceinline__ float lse2_acc(float a, float b) {  // prep only
    float mx = fmaxf(a, b);
    float mn = fminf(a, b);
    return mx + log1pf(expf(mn - mx));
}

// ---------------- fused prep: blocks 0..NN-1 = tokens, block NN = constants ----------------
__global__ void prep(const float* __restrict__ anc,
                     const float* __restrict__ ins,
                     const float* __restrict__ rr,
                     const float* __restrict__ uu,
                     const float* __restrict__ data) {
    int b = blockIdx.x;
    if (b < NN) {
        int t = threadIdx.x;
        const float* row = data + ((size_t)(b * LL + t)) * DD;
        int tk = DD;                                // padding -> emission 1.0 row
        for (int d = 0; d < DD; d++)
            if (row[d] > 0.5f) tk = d;
        g_tok[b * LL + t] = tk;
        return;
    }

    int m = threadIdx.x;
    if (m < MSTRIDE) {                              // padding row: prob 1
        g_Ea[DD * MSTRIDE + m] = 1.0f;
        g_Ei[DD * MSTRIDE + m] = 1.0f;
    }
    if (m >= MP1) return;

    {
        const float* ar = anc + m * DD;
        float mx = -1e30f;
        for (int d = 0; d < DD; d++) mx = fmaxf(mx, ar[d]);
        float s = 0.f;
        for (int d = 0; d < DD; d++) s += expf(ar[d] - mx);
        float lse = mx + logf(s);
        for (int d = 0; d < DD; d++) g_Ea[d * MSTRIDE + m] = expf(ar[d] - lse);
    }
    {
        const float* ir = ins + m * DD;
        float mx = -1e30f;
        for (int d = 0; d < DD; d++) mx = fmaxf(mx, ir[d]);
        float s = 0.f;
        for (int d = 0; d < DD; d++) s += expf(ir[d] - mx);
        float lse = mx + logf(s);
        for (int d = 0; d < DD; d++) g_Ei[d * MSTRIDE + m] = expf(ir[d] - lse);
    }

    float r[3][2], u[3][2];
    for (int c = 0; c < 3; c++) {
        float x0 = rr[(m * 3 + c) * 2 + 0];
        float x1 = rr[(m * 3 + c) * 2 + 1];
        float l2 = lse2_acc(x0, x1);
        r[c][0] = x0 - l2; r[c][1] = x1 - l2;
        x0 = uu[(m * 3 + c) * 2 + 0];
        x1 = uu[(m * 3 + c) * 2 + 1];
        l2 = lse2_acc(x0, x1);
        u[c][0] = x0 - l2; u[c][1] = x1 - l2;
    }
    g_w  [m] = expf(r[2][0] + u[2][1]);
    g_cb0[m] = expf(r[0][0] + u[0][1]);
    g_cb1[m] = expf(r[1][0] + u[1][1]);
    g_q00[m] = expf(r[0][0] + u[0][0]);
    g_q10[m] = expf(r[1][0] + u[1][0]);
    g_q01[m] = expf(r[0][1]);
    g_q11[m] = expf(r[1][1]);
    g_c0 [m] = expf(r[2][0] + u[2][0]);
    g_c1 [m] = expf(r[2][1]);
}

// ---------------- main: 4 warps/block (one per SMSP), one sequence per warp ----------------
__global__ void __launch_bounds__(128) hmm_fwd(float* __restrict__ out) {
    const unsigned FULL = 0xffffffffu;
    const int wid = threadIdx.x >> 5;
    const int n = blockIdx.x * 4 + wid;
    const int l = threadIdx.x & 31;
    const int m0 = l * 4;
    const bool lastlane = (l == 31);

    // per-element probability constants
    float cb0[4], cb1[4], wv[4], q00[4], q10[4], q01[4], q11[4], c0[4], c1[4];
#pragma unroll
    for (int q = 0; q < 4; q++) {
        int m = m0 + q;
        cb0[q] = g_cb0[m]; cb1[q] = g_cb1[m]; wv[q] = g_w[m];
        q00[q] = g_q00[m]; q10[q] = g_q10[m];
        q01[q] = g_q01[m]; q11[q] = g_q11[m];
        c0[q]  = g_c0[m];  c1[q]  = g_c1[m];
    }
    const float q00x = lastlane ? g_q00[MM] : 0.f;
    const float q10x = lastlane ? g_q10[MM] : 0.f;
    const float q01x = lastlane ? g_q01[MM] : 0.f;
    const float q11x = lastlane ? g_q11[MM] : 0.f;
    const float c0x  = lastlane ? g_c0 [MM] : 0.f;
    const float c1x  = lastlane ? g_c1 [MM] : 0.f;

    const float wv0 = wv[0], wv1 = wv[1], wv2 = wv[2], wv3 = wv[3];
    const float W23  = wv2 * wv3;
    const float W12  = wv1 * wv2;
    const float Wp1  = wv0 * wv1;
    const float Wp2  = Wp1 * wv2;
    const float W123 = wv1 * W23;
    const float cbW0 = cb0[0] * W123;
    const float cbW1 = cb1[0] * W123;

    // lane-aggregate multiplier in log2; warp prefix; K constants as (m, e) pairs
    float Lwl = log2f(wv0 * W123);
    float P = Lwl;
#pragma unroll
    for (int d = 1; d < 32; d <<= 1) {
        float o = __shfl_up_sync(FULL, P, d);
        if (l >= d) P += o;
    }
    // radix-8 round offsets 1..7, then radix-4 round offsets 8,16,24
    float Km[10]; int Ke[10];
    {
        const int offs[10] = {1, 2, 3, 4, 5, 6, 7, 8, 16, 24};
#pragma unroll
        for (int j = 0; j < 10; j++) {
            float Po = __shfl_up_sync(FULL, P, offs[j]);
            if (l >= offs[j]) {
                float Kl = P - Po;
                float fe = floorf(Kl);
                Ke[j] = (int)fe;
                Km[j] = exp2f(Kl - fe);
            } else { Km[j] = 0.f; Ke[j] = EMINE; }
        }
    }

    // state: pair-shared exponents (a0m, a1m, ae) per element
    float a0m[4] = {0.f, 0.f, 0.f, 0.f}, a1m[4] = {0.f, 0.f, 0.f, 0.f};
    int   ae[4]  = {EMINE, EMINE, EMINE, EMINE};
    float axm0 = 0.f, axm1 = 0.f;
    int   axe = EMINE;
    float srcm = 1.0f; int srce = 0;

    const int* tn = g_tok + n * LL;

    for (int tt = 0; tt < LL; tt += 4) {
        const int4 tk4 = *(const int4*)(tn + tt);
        const int tks[4] = {tk4.x, tk4.y, tk4.z, tk4.w};

#pragma unroll
        for (int k = 0; k < 4; k++) {
            const int tko = tks[k] * MSTRIDE;

            float atopm = __shfl_up_sync(FULL, a0m[3], 1);
            int   atope = __shfl_up_sync(FULL, ae[3], 1);
            if (l == 0) { atopm = srcm; atope = srce; }

            // per-element: align prev-match (P) and same-pos insert (I); derive b, t0, t1
            float bm[4], t0[4], t1[4], u0;
            int e2[4];
#pragma unroll
            for (int i = 0; i < 4; i++) {
                float Pm = (i == 0) ? atopm : a0m[i - 1];
                int   Pe = (i == 0) ? atope : ae[i - 1];
                int e = max(Pe, ae[i]);
                float ps = escf(Pm, Pe - e);
                float is = escf(a1m[i], ae[i] - e);
                e2[i] = e;
                bm[i] = ps * cb0[i] + is * cb1[i];
                t0[i] = ps * q00[i] + is * q10[i];
                t1[i] = ps * q01[i] + is * q11[i];
                if (i == 0) u0 = ps * cbW0 + is * cbW1;
            }
            // m=128 element
            int e2x = max(ae[3], axe);
            float psx = escf(a0m[3], ae[3] - e2x);
            float isx = escf(axm1, axe - e2x);
            float t0x = psx * q00x + isx * q10x;
            float t1x = psx * q01x + isx * q11x;

            // lane aggregate injection Bs
            int Bse = max(max(e2[0], e2[1]), max(e2[2], e2[3]));
            float Bsm = escf(u0, e2[0] - Bse) + escf(bm[1] * W23, e2[1] - Bse)
                      + escf(bm[2] * wv3, e2[2] - Bse) + escf(bm[3], e2[3] - Bse);

            // warp scan: radix-8 round (offsets 1..7), then radix-4 round (8,16,24)
            {
                float om[7]; int oe[7];
#pragma unroll
                for (int j = 0; j < 7; j++) {
                    om[j] = __shfl_up_sync(FULL, Bsm, j + 1) * Km[j];
                    oe[j] = __shfl_up_sync(FULL, Bse, j + 1) + Ke[j];
                }
                int E = Bse;
#pragma unroll
                for (int j = 0; j < 7; j++) E = max(E, oe[j]);
                float s = escf(Bsm, Bse - E);
#pragma unroll
                for (int j = 0; j < 7; j++) s += escf(om[j], oe[j] - E);
                Bsm = s; Bse = E;

                float p1m = __shfl_up_sync(FULL, Bsm, 8)  * Km[7];
                int   p1e = __shfl_up_sync(FULL, Bse, 8)  + Ke[7];
                float p2m = __shfl_up_sync(FULL, Bsm, 16) * Km[8];
                int   p2e = __shfl_up_sync(FULL, Bse, 16) + Ke[8];
                float p3m = __shfl_up_sync(FULL, Bsm, 24) * Km[9];
                int   p3e = __shfl_up_sync(FULL, Bse, 24) + Ke[9];
                E = max(max(Bse, p1e), max(p2e, p3e));
                Bsm = escf(Bsm, Bse - E) + escf(p1m, p1e - E)
                    + escf(p2m, p2e - E) + escf(p3m, p3e - E);
                Bse = E;
            }
            float Bexm = __shfl_up_sync(FULL, Bsm, 1);
            int   Bexe = __shfl_up_sync(FULL, Bse, 1);
            if (l == 0) { Bexm = 0.f; Bexe = EMINE; }

            // per-element chain values B1..B3 (B0 = Bex)
            int Be1 = max(Bexe, e2[0]);
            float B1m = escf(Bexm * wv0, Bexe - Be1) + escf(bm[0], e2[0] - Be1);
            int Be2 = max(max(Bexe, e2[0]), e2[1]);
            float B2m = escf(Bexm * Wp1, Bexe - Be2) + escf(bm[0] * wv1, e2[0] - Be2)
                      + escf(bm[1], e2[1] - Be2);
            int Be3 = max(max(Bexe, e2[0]), max(e2[1], e2[2]));
            float B3m = escf(Bexm * Wp2, Bexe - Be3) + escf(bm[0] * W12, e2[0] - Be3)
                      + escf(bm[1] * wv2, e2[1] - Be3) + escf(bm[2], e2[2] - Be3);

            // emission probs
            const float4 ea = *(const float4*)(g_Ea + tko + m0);
            const float4 ei = *(const float4*)(g_Ei + tko + m0);
            const float eax = g_Ea[tko + MM];
            const float eix = g_Ei[tko + MM];
            const float eav[4] = {ea.x, ea.y, ea.z, ea.w};
            const float eiv[4] = {ei.x, ei.y, ei.z, ei.w};
            const float Bmv[4] = {Bexm, B1m, B2m, B3m};
            const int   Bev[4] = {Bexe, Be1, Be2, Be3};

            // new alphas (no per-step renorm; pair shares exponent E)
#pragma unroll
            for (int i = 0; i < 4; i++) {
                int E = max(e2[i], Bev[i]);
                float zs = escf(Bmv[i], Bev[i] - E);
                int kk = e2[i] - E;
                float s0 = escf(t0[i], kk) + zs * c0[i];
                float s1 = escf(t1[i], kk) + zs * c1[i];
                a0m[i] = s0 * eav[i];
                a1m[i] = s1 * eiv[i];
                ae[i] = E;
            }
            {
                int E = max(e2x, Bse);
                float zs = escf(Bsm, Bse - E);
                int kk = e2x - E;
                axm0 = (escf(t0x, kk) + zs * c0x) * eax;
                axm1 = (escf(t1x, kk) + zs * c1x) * eix;
                axe = E;
            }
            srcm = 0.f; srce = EMINE;

            // renormalize every 2 steps (mantissa drift bounded in [2^-90, 2^6])
            if (k & 1) {
#pragma unroll
                for (int i = 0; i < 4; i++) enorm2(a0m[i], a1m[i], ae[i]);
                enorm2(axm0, axm1, axe);
            }
        }
    }

    // final logsumexp over all states
    int emax = axe;
#pragma unroll
    for (int q = 0; q < 4; q++) emax = max(emax, ae[q]);
#pragma unroll
    for (int d = 16; d; d >>= 1) emax = max(emax, __shfl_xor_sync(FULL, emax, d));

    float s = escf(axm0, axe - emax) + escf(axm1, axe - emax);
#pragma unroll
    for (int q = 0; q < 4; q++)
        s += escf(a0m[q], ae[q] - emax) + escf(a1m[q], ae[q] - emax);
#pragma unroll
    for (int d = 16; d; d >>= 1) s += __shfl_xor_sync(FULL, s, d);

    if (l == 0) out[n] = ((float)emax + log2f(s)) * LN2;
}

// ---------------- entry point ----------------
extern "C" void kernel_launch(void* const* d_in, const int* in_sizes, int n_in,
                              void* d_out, int out_size) {
    const float* anc  = (const float*)d_in[0];  // (129, 24)
    const float* ins  = (const float*)d_in[1];  // (129, 24)
    const float* rr   = (const float*)d_in[2];  // (129, 3, 2)
    const float* uu   = (const float*)d_in[3];  // (129, 3, 2)
    const float* data = (const float*)d_in[4];  // (512, 256, 24)
    (void)in_sizes; (void)n_in; (void)out_size;

    prep<<<NN + 1, LL>>>(anc, ins, rr, uu, data);
    hmm_fwd<<<NN / 4, 128>>>((float*)d_out);
}

// round 10
// speedup vs baseline: 3.0706x; 1.1109x over previous
#include <cuda_runtime.h>
#include <math.h>

#define MM      128
#define MP1     129
#define DD      24
#define NN      512
#define LL      256
#define MSTRIDE 132

#define EMINE   (-(1 << 27))
#define LOG2E   1.4426950408889634f
#define LN2     0.6931471805599453f

// ---------------- device-global scratch (probability domain) ----------------
__device__ __align__(16) float g_cb0[MSTRIDE];
__device__ __align__(16) float g_cb1[MSTRIDE];
__device__ __align__(16) float g_w  [MSTRIDE];
__device__ __align__(16) float g_q00[MSTRIDE];
__device__ __align__(16) float g_q10[MSTRIDE];
__device__ __align__(16) float g_q01[MSTRIDE];
__device__ __align__(16) float g_q11[MSTRIDE];
__device__ __align__(16) float g_c0 [MSTRIDE];
__device__ __align__(16) float g_c1 [MSTRIDE];
__device__ __align__(16) float g_Ea [(DD + 1) * MSTRIDE];  // emission probs; row DD = 1.0 (padding)
__device__ __align__(16) float g_Ei [(DD + 1) * MSTRIDE];
__device__ __align__(16) int   g_tok[NN * LL];

struct FalseT { static constexpr bool value = false; };
struct TrueT  { static constexpr bool value = true;  };

// ---- extended float primitives: value = m * 2^e ----
__device__ __forceinline__ float escf(float x, int k) {
    k = max(k, -140);
    int b = __float_as_int(x) + (k << 23);
    return __int_as_float(max(b, 0x00800000));
}
__device__ __forceinline__ void enorm2(float& m0, float& m1, int& e) {
    float mx = fmaxf(m0, m1);
    int k = (__float_as_int(mx) >> 23) - 127;
    int s = k << 23;
    m0 = __int_as_float(max(__float_as_int(m0) - s, 0));
    m1 = __int_as_float(max(__float_as_int(m1) - s, 0));
    e += k;
}
__device__ __forceinline__ void enorm1(float& m, int& e) {
    int b = __float_as_int(m);
    int k = (b >> 23) - 127;
    e += k;
    m = __int_as_float(b - (k << 23));
}

__device__ __forceinline__ float lse2_acc(float a, float b) {  // prep only
    float mx = fmaxf(a, b);
    float mn = fminf(a, b);
    return mx + log1pf(expf(mn - mx));
}

// ---------------- fused prep ----------------
__global__ void prep(const float* __restrict__ anc,
                     const float* __restrict__ ins,
                     const float* __restrict__ rr,
                     const float* __restrict__ uu,
                     const float* __restrict__ data) {
    int b = blockIdx.x;
    if (b < NN) {
        int t = threadIdx.x;
        const float* row = data + ((size_t)(b * LL + t)) * DD;
        int tk = DD;
        for (int d = 0; d < DD; d++)
            if (row[d] > 0.5f) tk = d;
        g_tok[b * LL + t] = tk;
        return;
    }

    int m = threadIdx.x;
    if (m < MSTRIDE) {
        g_Ea[DD * MSTRIDE + m] = 1.0f;
        g_Ei[DD * MSTRIDE + m] = 1.0f;
    }
    if (m >= MP1) return;

    {
        const float* ar = anc + m * DD;
        float mx = -1e30f;
        for (int d = 0; d < DD; d++) mx = fmaxf(mx, ar[d]);
        float s = 0.f;
        for (int d = 0; d < DD; d++) s += expf(ar[d] - mx);
        float lse = mx + logf(s);
        for (int d = 0; d < DD; d++) g_Ea[d * MSTRIDE + m] = expf(ar[d] - lse);
    }
    {
        const float* ir = ins + m * DD;
        float mx = -1e30f;
        for (int d = 0; d < DD; d++) mx = fmaxf(mx, ir[d]);
        float s = 0.f;
        for (int d = 0; d < DD; d++) s += expf(ir[d] - mx);
        float lse = mx + logf(s);
        for (int d = 0; d < DD; d++) g_Ei[d * MSTRIDE + m] = expf(ir[d] - lse);
    }

    float r[3][2], u[3][2];
    for (int c = 0; c < 3; c++) {
        float x0 = rr[(m * 3 + c) * 2 + 0];
        float x1 = rr[(m * 3 + c) * 2 + 1];
        float l2 = lse2_acc(x0, x1);
        r[c][0] = x0 - l2; r[c][1] = x1 - l2;
        x0 = uu[(m * 3 + c) * 2 + 0];
        x1 = uu[(m * 3 + c) * 2 + 1];
        l2 = lse2_acc(x0, x1);
        u[c][0] = x0 - l2; u[c][1] = x1 - l2;
    }
    g_w  [m] = expf(r[2][0] + u[2][1]);
    g_cb0[m] = expf(r[0][0] + u[0][1]);
    g_cb1[m] = expf(r[1][0] + u[1][1]);
    g_q00[m] = expf(r[0][0] + u[0][0]);
    g_q10[m] = expf(r[1][0] + u[1][0]);
    g_q01[m] = expf(r[0][1]);
    g_q11[m] = expf(r[1][1]);
    g_c0 [m] = expf(r[2][0] + u[2][0]);
    g_c1 [m] = expf(r[2][1]);
}

// ---------------- main: 4 warps/block (one per SMSP), one sequence per warp ----------------
__global__ void __launch_bounds__(128) hmm_fwd(float* __restrict__ out) {
    const unsigned FULL = 0xffffffffu;
    const int wid = threadIdx.x >> 5;
    const int n = blockIdx.x * 4 + wid;
    const int l = threadIdx.x & 31;
    const int m0 = l * 4;
    const bool lastlane = (l == 31);

    float cb0[4], cb1[4], wv[4], q00[4], q10[4], q01[4], q11[4], c0[4], c1[4];
#pragma unroll
    for (int q = 0; q < 4; q++) {
        int m = m0 + q;
        cb0[q] = g_cb0[m]; cb1[q] = g_cb1[m]; wv[q] = g_w[m];
        q00[q] = g_q00[m]; q10[q] = g_q10[m];
        q01[q] = g_q01[m]; q11[q] = g_q11[m];
        c0[q]  = g_c0[m];  c1[q]  = g_c1[m];
    }
    const float q00x = lastlane ? g_q00[MM] : 0.f;
    const float q10x = lastlane ? g_q10[MM] : 0.f;
    const float q01x = lastlane ? g_q01[MM] : 0.f;
    const float q11x = lastlane ? g_q11[MM] : 0.f;
    const float c0x  = lastlane ? g_c0 [MM] : 0.f;
    const float c1x  = lastlane ? g_c1 [MM] : 0.f;

    const float wv0 = wv[0], wv1 = wv[1], wv2 = wv[2], wv3 = wv[3];
    const float W23  = wv2 * wv3;
    const float W123 = wv1 * W23;
    const float cbW0 = cb0[0] * W123;
    const float cbW1 = cb1[0] * W123;

    // lane-aggregate multiplier in log2; warp prefix; scan K constants as (m, e)
    float Lwl = log2f(wv0 * W123);
    float P = Lwl;
#pragma unroll
    for (int d = 1; d < 32; d <<= 1) {
        float o = __shfl_up_sync(FULL, P, d);
        if (l >= d) P += o;
    }
    float Km[10]; int Ke[10];
    {
        const int offs[10] = {1, 2, 3, 4, 5, 6, 7, 8, 16, 24};
#pragma unroll
        for (int j = 0; j < 10; j++) {
            float Po = __shfl_up_sync(FULL, P, offs[j]);
            if (l >= offs[j]) {
                float Kl = P - Po;
                float fe = floorf(Kl);
                Ke[j] = (int)fe;
                Km[j] = exp2f(Kl - fe);
            } else { Km[j] = 0.f; Ke[j] = EMINE; }
        }
    }

    // state
    float a0m[4] = {0.f, 0.f, 0.f, 0.f}, a1m[4] = {0.f, 0.f, 0.f, 0.f};
    int   ae[4]  = {EMINE, EMINE, EMINE, EMINE};
    float axm1 = 0.f; int axe = EMINE;      // insert state m=128
    float axm0 = 0.f; int axe0 = EMINE;     // match state m=128 (final step only)
    float srcm = 1.0f; int srce = 0;

    const int* tn = g_tok + n * LL;

    // one HMM step; LAST variant additionally computes the m=128 match state
    auto step = [&](int tkoC, float4 eaC, float4 eiC, float eixC, auto LASTC) {
        constexpr bool LAST = decltype(LASTC)::value;

        float atopm = __shfl_up_sync(FULL, a0m[3], 1);
        int   atope = __shfl_up_sync(FULL, ae[3], 1);
        if (l == 0) { atopm = srcm; atope = srce; }

        float bm[4], t0[4], t1[4], u0;
        int e2[4];
#pragma unroll
        for (int i = 0; i < 4; i++) {
            float Pm = (i == 0) ? atopm : a0m[i - 1];
            int   Pe = (i == 0) ? atope : ae[i - 1];
            int e = max(Pe, ae[i]);
            float ps = escf(Pm, Pe - e);
            float is = escf(a1m[i], ae[i] - e);
            e2[i] = e;
            bm[i] = ps * cb0[i] + is * cb1[i];
            t0[i] = ps * q00[i] + is * q10[i];
            t1[i] = ps * q01[i] + is * q11[i];
            if (i == 0) u0 = ps * cbW0 + is * cbW1;
        }
        // m=128 element (insert only during mainloop)
        int e2x = max(ae[3], axe);
        float psx = escf(a0m[3], ae[3] - e2x);
        float isx = escf(axm1, axe - e2x);
        float t1x = psx * q01x + isx * q11x;
        float t0x = 0.f;
        if (LAST) t0x = psx * q00x + isx * q10x;

        // lane aggregate injection
        int Bse = max(max(e2[0], e2[1]), max(e2[2], e2[3]));
        float Bsm = escf(u0, e2[0] - Bse) + escf(bm[1] * W23, e2[1] - Bse)
                  + escf(bm[2] * wv3, e2[2] - Bse) + escf(bm[3], e2[3] - Bse);

        // warp scan: radix-8 round (offsets 1..7), then radix-4 round (8,16,24)
        {
            float om[7]; int oe[7];
#pragma unroll
            for (int j = 0; j < 7; j++) {
                om[j] = __shfl_up_sync(FULL, Bsm, j + 1) * Km[j];
                oe[j] = __shfl_up_sync(FULL, Bse, j + 1) + Ke[j];
            }
            int E = Bse;
#pragma unroll
            for (int j = 0; j < 7; j++) E = max(E, oe[j]);
            float s = escf(Bsm, Bse - E);
#pragma unroll
            for (int j = 0; j < 7; j++) s += escf(om[j], oe[j] - E);
            Bsm = s; Bse = E;

            float p1m = __shfl_up_sync(FULL, Bsm, 8)  * Km[7];
            int   p1e = __shfl_up_sync(FULL, Bse, 8)  + Ke[7];
            float p2m = __shfl_up_sync(FULL, Bsm, 16) * Km[8];
            int   p2e = __shfl_up_sync(FULL, Bse, 16) + Ke[8];
            float p3m = __shfl_up_sync(FULL, Bsm, 24) * Km[9];
            int   p3e = __shfl_up_sync(FULL, Bse, 24) + Ke[9];
            E = max(max(Bse, p1e), max(p2e, p3e));
            Bsm = escf(Bsm, Bse - E) + escf(p1m, p1e - E)
                + escf(p2m, p2e - E) + escf(p3m, p3e - E);
            Bse = E;
        }
        float Bexm = __shfl_up_sync(FULL, Bsm, 1);
        int   Bexe = __shfl_up_sync(FULL, Bse, 1);
        if (l == 0) { Bexm = 0.f; Bexe = EMINE; }

        // recurrent B-chain: exact same scales as per-B max trees
        int Be1 = max(Bexe, e2[0]);
        float B1m = escf(Bexm, Bexe - Be1) * wv0 + escf(bm[0], e2[0] - Be1);
        int Be2 = max(Be1, e2[1]);
        float B2m = escf(B1m, Be1 - Be2) * wv1 + escf(bm[1], e2[1] - Be2);
        int Be3 = max(Be2, e2[2]);
        float B3m = escf(B2m, Be2 - Be3) * wv2 + escf(bm[2], e2[2] - Be3);

        const float eav[4] = {eaC.x, eaC.y, eaC.z, eaC.w};
        const float eiv[4] = {eiC.x, eiC.y, eiC.z, eiC.w};
        const float Bmv[4] = {Bexm, B1m, B2m, B3m};
        const int   Bev[4] = {Bexe, Be1, Be2, Be3};

#pragma unroll
        for (int i = 0; i < 4; i++) {
            int E = max(e2[i], Bev[i]);
            float zs = escf(Bmv[i], Bev[i] - E);
            int kk = e2[i] - E;
            float s0 = escf(t0[i], kk) + zs * c0[i];
            float s1 = escf(t1[i], kk) + zs * c1[i];
            a0m[i] = s0 * eav[i];
            a1m[i] = s1 * eiv[i];
            ae[i] = E;
        }
        {
            int E = max(e2x, Bse);
            float zs = escf(Bsm, Bse - E);
            int kk = e2x - E;
            axm1 = (escf(t1x, kk) + zs * c1x) * eixC;
            if (LAST) {
                float eax = g_Ea[tkoC + MM];
                axm0 = (escf(t0x, kk) + zs * c0x) * eax;
                axe0 = E;
            }
            axe = E;
        }
        srcm = 0.f; srce = EMINE;
    };

    // ---------------- pipelined mainloop ----------------
    int4 tkc = *(const int4*)(tn);
    int tko = tkc.x * MSTRIDE;
    float4 ea = *(const float4*)(g_Ea + tko + m0);
    float4 ei = *(const float4*)(g_Ei + tko + m0);
    float eix = g_Ei[tko + MM];

    for (int tt = 0; tt < LL - 4; tt += 4) {
        const int4 tkn = *(const int4*)(tn + tt + 4);
        const int ct[4] = {tkc.x, tkc.y, tkc.z, tkc.w};
        const int nt[4] = {tkc.y, tkc.z, tkc.w, tkn.x};
#pragma unroll
        for (int k = 0; k < 4; k++) {
            // prefetch next step's emissions
            const int tko2 = nt[k] * MSTRIDE;
            const float4 ea2 = *(const float4*)(g_Ea + tko2 + m0);
            const float4 ei2 = *(const float4*)(g_Ei + tko2 + m0);
            const float eix2 = g_Ei[tko2 + MM];

            step(ct[k] * MSTRIDE, ea, ei, eix, FalseT{});
            ea = ea2; ei = ei2; eix = eix2;

            if (k & 1) {
#pragma unroll
                for (int i = 0; i < 4; i++) enorm2(a0m[i], a1m[i], ae[i]);
                enorm1(axm1, axe);
            }
        }
        tkc = tkn;
    }
    // final group (tt = LL-4): steps 252..255; 255 also computes a0x
    {
        const int ct[4] = {tkc.x, tkc.y, tkc.z, tkc.w};
#pragma unroll
        for (int k = 0; k < 3; k++) {
            const int tko2 = ct[k + 1] * MSTRIDE;
            const float4 ea2 = *(const float4*)(g_Ea + tko2 + m0);
            const float4 ei2 = *(const float4*)(g_Ei + tko2 + m0);
            const float eix2 = g_Ei[tko2 + MM];
            step(ct[k] * MSTRIDE, ea, ei, eix, FalseT{});
            ea = ea2; ei = ei2; eix = eix2;
            if (k & 1) {
#pragma unroll
                for (int i = 0; i < 4; i++) enorm2(a0m[i], a1m[i], ae[i]);
                enorm1(axm1, axe);
            }
        }
        step(ct[3] * MSTRIDE, ea, ei, eix, TrueT{});
    }

    // final logsumexp over all states
    int emax = max(axe, axe0);
#pragma unroll
    for (int q = 0; q < 4; q++) emax = max(emax, ae[q]);
#pragma unroll
    for (int d = 16; d; d >>= 1) emax = max(emax, __shfl_xor_sync(FULL, emax, d));

    float s = escf(axm0, axe0 - emax) + escf(axm1, axe - emax);
#pragma unroll
    for (int q = 0; q < 4; q++)
        s += escf(a0m[q], ae[q] - emax) + escf(a1m[q], ae[q] - emax);
#pragma unroll
    for (int d = 16; d; d >>= 1) s += __shfl_xor_sync(FULL, s, d);

    if (l == 0) out[n] = ((float)emax + log2f(s)) * LN2;
}

// ---------------- entry point ----------------
extern "C" void kernel_launch(void* const* d_in, const int* in_sizes, int n_in,
                              void* d_out, int out_size) {
    const float* anc  = (const float*)d_in[0];  // (129, 24)
    const float* ins  = (const float*)d_in[1];  // (129, 24)
    const float* rr   = (const float*)d_in[2];  // (129, 3, 2)
    const float* uu   = (const float*)d_in[3];  // (129, 3, 2)
    const float* data = (const float*)d_in[4];  // (512, 256, 24)
    (void)in_sizes; (void)n_in; (void)out_size;

    prep<<<NN + 1, LL>>>(anc, ins, rr, uu, data);
    hmm_fwd<<<NN / 4, 128>>>((float*)d_out);
}